// round 5
// baseline (speedup 1.0000x reference)
#include <cuda_runtime.h>
#include <cstdint>

#define HDIM 128
#define WDIM 128
#define CDIM 256

#define A_STRIDE 132                     // words; ldmatrix rows 4j+c banks, conflict-free
#define B_STRIDE 132                     // words; B frag banks 4*lc+lr, conflict-free
#define KCHUNK 32
#define A_WORDS (128 * A_STRIDE)         // 16896
#define B_WORDS (KCHUNK * B_STRIDE)      // 4224 per buffer
#define SMEM_BYTES ((A_WORDS + 2 * B_WORDS) * 4)   // 101376

static __device__ __forceinline__ uint32_t tf32u(float x) {
    uint32_t r;
    asm("cvt.rna.tf32.f32 %0, %1;" : "=r"(r) : "f"(x));
    return r;
}

static __device__ __forceinline__ void cp16(uint32_t dst, const void* src) {
    asm volatile("cp.async.ca.shared.global [%0], [%1], 16;" :: "r"(dst), "l"(src));
}

static __device__ __forceinline__ void ldsm_x4(uint32_t r[4], uint32_t addr) {
    asm volatile("ldmatrix.sync.aligned.m8n8.x4.shared.b16 {%0,%1,%2,%3}, [%4];"
                 : "=r"(r[0]), "=r"(r[1]), "=r"(r[2]), "=r"(r[3]) : "r"(addr));
}

static __device__ __forceinline__ void mma_tf32(float c[4], const uint32_t a[4],
                                                uint32_t b0, uint32_t b1) {
    asm volatile(
        "mma.sync.aligned.m16n8k8.row.col.f32.tf32.tf32.f32 "
        "{%0,%1,%2,%3}, {%4,%5,%6,%7}, {%8,%9}, {%0,%1,%2,%3};"
        : "+f"(c[0]), "+f"(c[1]), "+f"(c[2]), "+f"(c[3])
        : "r"(a[0]), "r"(a[1]), "r"(a[2]), "r"(a[3]), "r"(b0), "r"(b1));
}

// ---------------------------------------------------------------------------
// CTA = (nh, rc, b): D[128 rows, 128 cols] = softmax(attn+gauss) @ V[:, nh*128..]
// 8 warps, warp w -> 64x32 slab: rows (w&1)*64, cols (w>>1)*32.
// V streamed in 4 k-chunks of 32, double-buffered cp.async.
// ---------------------------------------------------------------------------
__global__ void __launch_bounds__(256, 2) gt_mma(
    const float* __restrict__ attn, const float* __restrict__ V,
    const float* __restrict__ sp, const float* __restrict__ bp,
    float* __restrict__ out, int term)
{
    extern __shared__ uint32_t smem[];
    uint32_t* As = smem;                                   // [128][132]
    uint32_t* Bs0 = smem + A_WORDS;                        // [32][132] x2
    const uint32_t As_u  = (uint32_t)__cvta_generic_to_shared(As);
    const uint32_t Bs_u  = (uint32_t)__cvta_generic_to_shared(Bs0);

    const int tid = threadIdx.x, lane = tid & 31, wid = tid >> 5;
    const int nh = blockIdx.x, rc = blockIdx.y, b = blockIdx.z;
    const float sh = sp[0], bi = bp[0];

    const float* abase = attn + ((size_t)b * 128 + rc) * (size_t)(128 * 128);
    const size_t vstride = term ? (size_t)(WDIM * CDIM) : (size_t)CDIM;
    const size_t tile_off = (term ? ((size_t)b * HDIM * WDIM * CDIM + (size_t)rc * CDIM)
                                  : ((size_t)b * 128 + rc) * (size_t)(WDIM * CDIM))
                            + (size_t)nh * 128;
    const float* vbase = V + tile_off;

    // ---- G0: attn tile (64KB) ----
    #pragma unroll
    for (int i = 0; i < 16; ++i) {
        int c = i * 256 + tid;           // 4096 16B chunks
        int row = c >> 5, q = c & 31;
        cp16(As_u + (uint32_t)row * (A_STRIDE * 4) + (uint32_t)q * 16,
             abase + row * 128 + q * 4);
    }
    asm volatile("cp.async.commit_group;" ::: "memory");

    // ---- G1, G2: V k-chunks 0 and 1 ----
    #pragma unroll
    for (int ch = 0; ch < 2; ++ch) {
        #pragma unroll
        for (int i = 0; i < 4; ++i) {
            int c = i * 256 + tid;       // 1024 16B chunks: 32 rows x 32 q
            int row = c >> 5, q = c & 31;
            cp16(Bs_u + (uint32_t)ch * (B_WORDS * 4)
                      + (uint32_t)row * (B_STRIDE * 4) + (uint32_t)q * 16,
                 vbase + (size_t)(ch * KCHUNK + row) * vstride + q * 4);
        }
        asm volatile("cp.async.commit_group;" ::: "memory");
    }

    // ---- softmax in place (V chunks still in flight) ----
    asm volatile("cp.async.wait_group 2;" ::: "memory");
    __syncthreads();

    #pragma unroll 1
    for (int rr = 0; rr < 16; ++rr) {
        int row = wid * 16 + rr;
        float4 v = *(const float4*)((const float*)As + row * A_STRIDE + lane * 4);
        float vv[4] = {v.x, v.y, v.z, v.w};
        float fr = (float)row;
        #pragma unroll
        for (int j = 0; j < 4; ++j) {
            float d = (float)(lane * 4 + j) - fr;
            vv[j] -= fmaf(sh, d * d, bi);
        }
        float m = fmaxf(fmaxf(vv[0], vv[1]), fmaxf(vv[2], vv[3]));
        #pragma unroll
        for (int o = 16; o > 0; o >>= 1) m = fmaxf(m, __shfl_xor_sync(~0u, m, o));
        float e[4]; float s = 0.f;
        #pragma unroll
        for (int j = 0; j < 4; ++j) { e[j] = __expf(vv[j] - m); s += e[j]; }
        #pragma unroll
        for (int o = 16; o > 0; o >>= 1) s += __shfl_xor_sync(~0u, s, o);
        float inv = 1.0f / s;
        uint4 w = make_uint4(tf32u(e[0] * inv), tf32u(e[1] * inv),
                             tf32u(e[2] * inv), tf32u(e[3] * inv));
        *(uint4*)(As + row * A_STRIDE + lane * 4) = w;
    }

    // ---- MMA over 4 k-chunks ----
    const int mh = (wid & 1) * 64;
    const int nq = (wid >> 1) * 32;
    const int lr = lane >> 2, lc = lane & 3;

    float acc[4][4][4];
    #pragma unroll
    for (int t = 0; t < 4; ++t)
        #pragma unroll
        for (int j = 0; j < 4; ++j)
            #pragma unroll
            for (int q = 0; q < 4; ++q) acc[t][j][q] = 0.f;

    // ldmatrix source address for this lane: matrix i=lane/8, row j=lane%8
    const int lm_mat = lane >> 3, lm_row = lane & 7;
    const int lm_roff = (lm_mat & 1) * 8 + lm_row;   // +8 rows for mats 1,3
    const int lm_koff = (lm_mat >> 1) * 4;           // +4 k for mats 2,3

    #pragma unroll 1
    for (int chunk = 0; chunk < 4; ++chunk) {
        if (chunk < 3)
            asm volatile("cp.async.wait_group 1;" ::: "memory");
        else
            asm volatile("cp.async.wait_group 0;" ::: "memory");
        __syncthreads();

        const uint32_t* Bsc = Bs0 + (chunk & 1) * B_WORDS;

        #pragma unroll
        for (int ks = 0; ks < 4; ++ks) {
            const int kc = chunk * KCHUNK + ks * 8;
            uint32_t a[4][4];
            #pragma unroll
            for (int t = 0; t < 4; ++t) {
                uint32_t addr = As_u + (uint32_t)((mh + t * 16 + lm_roff) * A_STRIDE
                                                  + kc + lm_koff) * 4;
                ldsm_x4(a[t], addr);
            }
            #pragma unroll
            for (int j = 0; j < 4; ++j) {
                const float* bp8 = (const float*)Bsc + (ks * 8 + lc) * B_STRIDE
                                   + nq + j * 8 + lr;
                uint32_t b0 = tf32u(bp8[0]);
                uint32_t b1 = tf32u(bp8[4 * B_STRIDE]);
                #pragma unroll
                for (int t = 0; t < 4; ++t)
                    mma_tf32(acc[t][j], a[t], b0, b1);
            }
        }

        __syncthreads();
        if (chunk < 2) {        // prefetch chunk+2 into the buffer just freed
            int nc = chunk + 2;
            #pragma unroll
            for (int i = 0; i < 4; ++i) {
                int c = i * 256 + tid;
                int row = c >> 5, q = c & 31;
                cp16(Bs_u + (uint32_t)(chunk & 1) * (B_WORDS * 4)
                          + (uint32_t)row * (B_STRIDE * 4) + (uint32_t)q * 16,
                     vbase + (size_t)(nc * KCHUNK + row) * vstride + q * 4);
            }
            asm volatile("cp.async.commit_group;" ::: "memory");
        }
    }

    // ---- epilogue: float2 stores (term2 RMW) ----
    float* obase = out + tile_off;
    const size_t ostride = vstride;
    #pragma unroll
    for (int t = 0; t < 4; ++t) {
        #pragma unroll
        for (int j = 0; j < 4; ++j) {
            int r0 = mh + t * 16 + lr;
            int col = nq + j * 8 + lc * 2;
            float* p0 = obase + (size_t)r0 * ostride + col;
            float* p1 = p0 + 8 * ostride;
            float2 v0 = make_float2(acc[t][j][0], acc[t][j][1]);
            float2 v1 = make_float2(acc[t][j][2], acc[t][j][3]);
            if (term) {
                float2 c0 = *(float2*)p0, c1 = *(float2*)p1;
                v0.x += c0.x; v0.y += c0.y;
                v1.x += c1.x; v1.y += c1.y;
            }
            *(float2*)p0 = v0;
            *(float2*)p1 = v1;
        }
    }
}

extern "C" void kernel_launch(void* const* d_in, const int* in_sizes, int n_in,
                              void* d_out, int out_size)
{
    const float* attn_x = (const float*)d_in[1];
    const float* attn_y = (const float*)d_in[2];
    const float* V      = (const float*)d_in[3];
    const float* sh     = (const float*)d_in[4];
    const float* bi     = (const float*)d_in[5];
    float* out          = (float*)d_out;

    const int B = in_sizes[3] / (HDIM * WDIM * CDIM);

    cudaFuncSetAttribute(gt_mma, cudaFuncAttributeMaxDynamicSharedMemorySize, SMEM_BYTES);

    dim3 grid(2, 128, B);                 // nh fastest -> attn-tile pair adjacent (L2 reuse)
    gt_mma<<<grid, 256, SMEM_BYTES>>>(attn_x, V, sh, bi, out, 0);
    gt_mma<<<grid, 256, SMEM_BYTES>>>(attn_y, V, sh, bi, out, 1);
}

// round 6
// speedup vs baseline: 1.0765x; 1.0765x over previous
#include <cuda_runtime.h>
#include <cstdint>

#define HDIM 128
#define WDIM 128
#define CDIM 256

#define A_STRIDE 132                     // words
#define B_STRIDE 264                     // words; frag banks lc*8+lr, conflict-free
#define KCHUNK 32
#define A_WORDS (128 * A_STRIDE)         // 16896
#define B_WORDS (KCHUNK * B_STRIDE)      // 8448
#define SMEM_BYTES ((2 * A_WORDS + 2 * B_WORDS) * 4)   // 202752

static __device__ __forceinline__ uint32_t tf32u(float x) {
    uint32_t r;
    asm("cvt.rna.tf32.f32 %0, %1;" : "=r"(r) : "f"(x));
    return r;
}
static __device__ __forceinline__ void cp16(uint32_t dst, const void* src) {
    asm volatile("cp.async.cg.shared.global [%0], [%1], 16;" :: "r"(dst), "l"(src));
}
#define CP_COMMIT() asm volatile("cp.async.commit_group;" ::: "memory")
#define CP_WAIT(n)  asm volatile("cp.async.wait_group %0;" :: "n"(n) : "memory")

static __device__ __forceinline__ void ldsm_x4(uint32_t r[4], uint32_t addr) {
    asm volatile("ldmatrix.sync.aligned.m8n8.x4.shared.b16 {%0,%1,%2,%3}, [%4];"
                 : "=r"(r[0]), "=r"(r[1]), "=r"(r[2]), "=r"(r[3]) : "r"(addr));
}
static __device__ __forceinline__ void mma_tf32(float c[4], const uint32_t a[4],
                                                uint32_t b0, uint32_t b1) {
    asm volatile(
        "mma.sync.aligned.m16n8k8.row.col.f32.tf32.tf32.f32 "
        "{%0,%1,%2,%3}, {%4,%5,%6,%7}, {%8,%9}, {%0,%1,%2,%3};"
        : "+f"(c[0]), "+f"(c[1]), "+f"(c[2]), "+f"(c[3])
        : "r"(a[0]), "r"(a[1]), "r"(a[2]), "r"(a[3]), "r"(b0), "r"(b1));
}

// ---------------------------------------------------------------------------
// Persistent kernel. Each CTA (512 thr) loops over tiles t = (b, rc) stride
// gridDim.x, computing D[128,256] = softmax(attn_t + gauss) @ V_t.
// A double-buffered (2x67.6KB), V double-buffered in 32-k chunks (2x33.8KB).
// cp.async group schedule (FIFO), steady state per tile:
//   [B(t,0)][B(t,1)] <head wait 2 = A(t) done> softmax
//   c0: wait1, MMA, issue A(t+1)+B(t,2)
//   c1: wait2(last:1), MMA, issue B(t,3)
//   c2: wait1, MMA, issue B(t+1,0)
//   c3: wait1(last:0), MMA, issue B(t+1,1)
//   epilogue stores
// ---------------------------------------------------------------------------
__global__ void __launch_bounds__(512, 1) gt_mma(
    const float* __restrict__ attn, const float* __restrict__ V,
    const float* __restrict__ sp, const float* __restrict__ bp,
    float* __restrict__ out, int term, int ntiles)
{
    extern __shared__ uint32_t smem[];
    uint32_t* Ab[2] = { smem, smem + A_WORDS };
    uint32_t* Bb[2] = { smem + 2 * A_WORDS, smem + 2 * A_WORDS + B_WORDS };
    uint32_t Au[2], Bu[2];
    Au[0] = (uint32_t)__cvta_generic_to_shared(Ab[0]);
    Au[1] = (uint32_t)__cvta_generic_to_shared(Ab[1]);
    Bu[0] = (uint32_t)__cvta_generic_to_shared(Bb[0]);
    Bu[1] = (uint32_t)__cvta_generic_to_shared(Bb[1]);

    const int tid = threadIdx.x, lane = tid & 31, wid = tid >> 5;
    const int nCta = gridDim.x;
    const float sh = sp[0], bi = bp[0];

    const size_t vstride = term ? (size_t)(WDIM * CDIM) : (size_t)CDIM;

    // tile address helpers
    auto abase = [&](int t) {
        int rc = t & 127, b = t >> 7;
        return attn + ((size_t)b * 128 + rc) * (size_t)(128 * 128);
    };
    auto toff = [&](int t) -> size_t {
        int rc = t & 127, b = t >> 7;
        return term ? ((size_t)b * HDIM * WDIM * CDIM + (size_t)rc * CDIM)
                    : ((size_t)b * 128 + rc) * (size_t)(WDIM * CDIM);
    };
    auto issue_A = [&](int t, int p) {
        const float* src = abase(t);
        #pragma unroll
        for (int i = 0; i < 8; ++i) {
            int c = i * 512 + tid;           // 4096 chunks
            int row = c >> 5, q = c & 31;
            cp16(Au[p] + (uint32_t)row * (A_STRIDE * 4) + (uint32_t)q * 16,
                 src + row * 128 + q * 4);
        }
        CP_COMMIT();
    };
    auto issue_B = [&](int t, int chunk, int buf) {
        const float* src = V + toff(t);
        #pragma unroll
        for (int i = 0; i < 4; ++i) {
            int c = i * 512 + tid;           // 2048 chunks: 32 rows x 64 q
            int row = c >> 6, q = c & 63;
            cp16(Bu[buf] + (uint32_t)row * (B_STRIDE * 4) + (uint32_t)q * 16,
                 src + (size_t)(chunk * KCHUNK + row) * vstride + q * 4);
        }
        CP_COMMIT();
    };

    int t = blockIdx.x;
    if (t >= ntiles) return;

    int p = 0;
    issue_A(t, 0);
    issue_B(t, 0, 0);
    issue_B(t, 1, 1);

    const int mh = (wid & 1) * 64;
    const int nq = (wid >> 1) * 32;
    const int lr = lane >> 2, lc = lane & 3;
    const int lm_mat = lane >> 3, lm_row = lane & 7;
    const int lm_roff = (lm_mat & 1) * 8 + lm_row;
    const int lm_koff = (lm_mat >> 1) * 4;

    #pragma unroll 1
    for (; t < ntiles; t += nCta) {
        const bool last = (t + nCta >= ntiles);
        const size_t off = toff(t);

        // ---- head: A(t) ready (B(t,0/1) may still be in flight) ----
        CP_WAIT(2);
        __syncthreads();

        // ---- softmax in place: 16 warps x 8 rows ----
        float* Af = (float*)Ab[p];
        #pragma unroll 1
        for (int rr = 0; rr < 8; ++rr) {
            int row = wid * 8 + rr;
            float4 v = *(const float4*)(Af + row * A_STRIDE + lane * 4);
            float vv[4] = {v.x, v.y, v.z, v.w};
            float fr = (float)row;
            #pragma unroll
            for (int j = 0; j < 4; ++j) {
                float d = (float)(lane * 4 + j) - fr;
                vv[j] -= fmaf(sh, d * d, bi);
            }
            float m = fmaxf(fmaxf(vv[0], vv[1]), fmaxf(vv[2], vv[3]));
            #pragma unroll
            for (int o = 16; o > 0; o >>= 1) m = fmaxf(m, __shfl_xor_sync(~0u, m, o));
            float e[4]; float s = 0.f;
            #pragma unroll
            for (int j = 0; j < 4; ++j) { e[j] = __expf(vv[j] - m); s += e[j]; }
            #pragma unroll
            for (int o = 16; o > 0; o >>= 1) s += __shfl_xor_sync(~0u, s, o);
            float inv = 1.0f / s;
            uint4 w = make_uint4(tf32u(e[0] * inv), tf32u(e[1] * inv),
                                 tf32u(e[2] * inv), tf32u(e[3] * inv));
            *(uint4*)(Ab[p] + row * A_STRIDE + lane * 4) = w;
        }
        __syncthreads();

        // ---- MMA over 4 k-chunks ----
        float acc[4][4][4];
        #pragma unroll
        for (int u = 0; u < 4; ++u)
            #pragma unroll
            for (int j = 0; j < 4; ++j)
                #pragma unroll
                for (int q = 0; q < 4; ++q) acc[u][j][q] = 0.f;

        #pragma unroll 1
        for (int c = 0; c < 4; ++c) {
            if (c == 1) { if (last) CP_WAIT(1); else CP_WAIT(2); }
            else if (c == 3) { if (last) CP_WAIT(0); else CP_WAIT(1); }
            else CP_WAIT(1);
            __syncthreads();

            const uint32_t* Bsc = Bb[c & 1];
            #pragma unroll
            for (int ks = 0; ks < 4; ++ks) {
                uint32_t a[4][4];
                #pragma unroll
                for (int u = 0; u < 4; ++u) {
                    uint32_t addr = Au[p] + (uint32_t)((mh + u * 16 + lm_roff) * A_STRIDE
                                                       + c * KCHUNK + ks * 8 + lm_koff) * 4;
                    ldsm_x4(a[u], addr);
                }
                #pragma unroll
                for (int j = 0; j < 4; ++j) {
                    const float* bp8 = (const float*)Bsc + (ks * 8 + lc) * B_STRIDE
                                       + nq + j * 8 + lr;
                    uint32_t b0 = tf32u(bp8[0]);
                    uint32_t b1 = tf32u(bp8[4 * B_STRIDE]);
                    #pragma unroll
                    for (int u = 0; u < 4; ++u)
                        mma_tf32(acc[u][j], a[u], b0, b1);
                }
            }
            __syncthreads();

            if (c == 0) {
                if (!last) issue_A(t + nCta, p ^ 1);
                issue_B(t, 2, 0);
            } else if (c == 1) {
                issue_B(t, 3, 1);
            } else if (c == 2) {
                if (!last) issue_B(t + nCta, 0, 0);
            } else {
                if (!last) issue_B(t + nCta, 1, 1);
            }
        }

        // ---- epilogue ----
        float* obase = out + off;
        #pragma unroll
        for (int u = 0; u < 4; ++u) {
            #pragma unroll
            for (int j = 0; j < 4; ++j) {
                int r0 = mh + u * 16 + lr;
                int col = nq + j * 8 + lc * 2;
                float* p0 = obase + (size_t)r0 * vstride + col;
                float* p1 = p0 + 8 * vstride;
                float2 v0 = make_float2(acc[u][j][0], acc[u][j][1]);
                float2 v1 = make_float2(acc[u][j][2], acc[u][j][3]);
                if (term) {
                    float2 c0 = *(float2*)p0, c1 = *(float2*)p1;
                    v0.x += c0.x; v0.y += c0.y;
                    v1.x += c1.x; v1.y += c1.y;
                }
                *(float2*)p0 = v0;
                *(float2*)p1 = v1;
            }
        }

        p ^= 1;
    }
}

extern "C" void kernel_launch(void* const* d_in, const int* in_sizes, int n_in,
                              void* d_out, int out_size)
{
    const float* attn_x = (const float*)d_in[1];
    const float* attn_y = (const float*)d_in[2];
    const float* V      = (const float*)d_in[3];
    const float* sh     = (const float*)d_in[4];
    const float* bi     = (const float*)d_in[5];
    float* out          = (float*)d_out;

    const int B = in_sizes[3] / (HDIM * WDIM * CDIM);
    const int ntiles = B * 128;

    int nsm = 148;
    cudaDeviceGetAttribute(&nsm, cudaDevAttrMultiProcessorCount, 0);
    int grid = nsm < ntiles ? nsm : ntiles;

    cudaFuncSetAttribute(gt_mma, cudaFuncAttributeMaxDynamicSharedMemorySize, SMEM_BYTES);

    gt_mma<<<grid, 512, SMEM_BYTES>>>(attn_x, V, sh, bi, out, 0, ntiles);
    gt_mma<<<grid, 512, SMEM_BYTES>>>(attn_y, V, sh, bi, out, 1, ntiles);
}